// round 7
// baseline (speedup 1.0000x reference)
#include <cuda_runtime.h>

#define TPB    128
#define CTILE  128                 // codes staged per tile
#define KDIM   64
#define NPTS   32768
#define NCODES 8192
#define NT     (NCODES / CTILE)    // 64 tiles

// One thread = one point (64 dims in registers). Block stages 128 codes in
// shared memory, computes their half-norms, then each thread scans the tile:
//   score = dot(x, c) - 0.5*||c||^2
// argmax(score) == argmin(||x - c||^2)  (||x||^2 constant per point).
// Output: index written as float32 (exactly representable, 0..8191).
__global__ __launch_bounds__(TPB)
void vq_simple_kernel(const float* __restrict__ lat,
                      const float* __restrict__ cb,
                      float* __restrict__ out) {
    __shared__ float4 scode[CTILE * (KDIM / 4)];   // 128 codes x 64 dims (32 KB)
    __shared__ float  sc2h[CTILE];                 // 0.5*||c||^2 per code

    const int tid = threadIdx.x;
    const int gid = blockIdx.x * TPB + tid;        // this thread's point

    // ---- point into registers (16 x float4, coalesced) ----
    float4 px[KDIM / 4];
    {
        const float4* lp = reinterpret_cast<const float4*>(lat) + (size_t)gid * (KDIM / 4);
#pragma unroll
        for (int q = 0; q < KDIM / 4; q++) px[q] = lp[q];
    }

    float bestv = -3.0e38f;
    int   besti = 0;

    const float4* cbq = reinterpret_cast<const float4*>(cb);

    for (int t = 0; t < NT; t++) {
        __syncthreads();   // previous tile fully consumed
        // ---- stage 128 codes (coalesced float4 loads) ----
#pragma unroll
        for (int i = 0; i < (CTILE * (KDIM / 4)) / TPB; i++) {   // 16 iters
            int idx = tid + i * TPB;
            scode[idx] = cbq[(size_t)t * CTILE * (KDIM / 4) + idx];
        }
        __syncthreads();

        // ---- half-norms: one code per thread (CTILE == TPB) ----
        {
            float s = 0.f;
#pragma unroll
            for (int q = 0; q < KDIM / 4; q++) {
                float4 v = scode[tid * (KDIM / 4) + q];
                s = fmaf(v.x, v.x, s);
                s = fmaf(v.y, v.y, s);
                s = fmaf(v.z, v.z, s);
                s = fmaf(v.w, v.w, s);
            }
            sc2h[tid] = 0.5f * s;
        }
        __syncthreads();

        // ---- scan tile: 4 rotating accumulators break the FFMA chain ----
        for (int c = 0; c < CTILE; c++) {
            float s0 = 0.f, s1 = 0.f, s2 = 0.f, s3 = 0.f;
#pragma unroll
            for (int q = 0; q < KDIM / 4; q++) {
                float4 cv = scode[c * (KDIM / 4) + q];   // LDS.128, warp-broadcast
                s0 = fmaf(px[q].x, cv.x, s0);
                s1 = fmaf(px[q].y, cv.y, s1);
                s2 = fmaf(px[q].z, cv.z, s2);
                s3 = fmaf(px[q].w, cv.w, s3);
            }
            float s = ((s0 + s1) + (s2 + s3)) - sc2h[c];
            int cidx = t * CTILE + c;
            if (s > bestv) { bestv = s; besti = cidx; }   // strict > keeps first
        }
    }

    out[gid] = (float)besti;     // index as float32 (lossless for 0..8191)
}

// ---------------- launch: robust input identification ----------------
// latents  : 2,097,152 elements (8,388,608 bytes)
// codebook :   524,288 elements (2,097,152 bytes)
// 524288 can ONLY be codebook-as-elements; 8388608 can ONLY be latents-as-bytes.
extern "C" void kernel_launch(void* const* d_in, const int* in_sizes, int n_in,
                              void* d_out, int out_size) {
    const float* lat = (const float*)d_in[0];
    const float* cb  = (n_in > 1) ? (const float*)d_in[1] : (const float*)d_in[0];

    int cb_idx = -1, lat_idx = -1;
    for (int i = 0; i < n_in; i++) {
        if (in_sizes[i] == 524288)  cb_idx  = i;   // codebook (element semantics)
        if (in_sizes[i] == 8388608) lat_idx = i;   // latents  (byte semantics)
    }
    if (cb_idx >= 0) {
        cb = (const float*)d_in[cb_idx];
        for (int i = 0; i < n_in; i++)
            if (i != cb_idx && (in_sizes[i] == 2097152 || in_sizes[i] == 8388608)) {
                lat = (const float*)d_in[i]; break;
            }
    } else if (lat_idx >= 0) {
        lat = (const float*)d_in[lat_idx];
        for (int i = 0; i < n_in; i++)
            if (i != lat_idx && in_sizes[i] == 2097152) { cb = (const float*)d_in[i]; break; }
    }

    float* out = (float*)d_out;
    vq_simple_kernel<<<NPTS / TPB, TPB>>>(lat, cb, out);
}

// round 8
// speedup vs baseline: 2.6386x; 2.6386x over previous
#include <cuda_runtime.h>

#define TPB    256
#define PTILE  128
#define CTILE  64
#define KDIM   64
#define K2     32                  // K in float2 (u64) steps
#define NT     (8192 / CTILE)      // 128 code tiles
#define NPTS   32768
#define NCODES 8192

__device__ float g_c2h[NCODES];    // 0.5 * ||c||^2

// ---------------- prekernel: half squared norms of codebook ----------------
__global__ void c2_kernel(const float* __restrict__ cb) {
    int i = blockIdx.x * blockDim.x + threadIdx.x;
    if (i >= NCODES) return;
    const float* row = cb + (size_t)i * KDIM;
    float s = 0.f;
#pragma unroll
    for (int j = 0; j < KDIM; j++) s = fmaf(row[j], row[j], s);
    g_c2h[i] = 0.5f * s;
}

// defined float-pair <-> u64 moves
__device__ __forceinline__ unsigned long long pack2(float x, float y) {
    unsigned long long r;
    asm("mov.b64 %0, {%1, %2};" : "=l"(r) : "f"(x), "f"(y));   // lo = x
    return r;
}
__device__ __forceinline__ void upk(unsigned long long v, float& x, float& y) {
    asm("mov.b64 {%0, %1}, %2;" : "=f"(x), "=f"(y) : "l"(v));
}
// packed dual-FMA: d.lo += a.lo*b.lo ; d.hi += a.hi*b.hi  (FFMA2)
__device__ __forceinline__ void ffma2(unsigned long long& d,
                                      unsigned long long a,
                                      unsigned long long b) {
    asm("fma.rn.f32x2 %0, %1, %2, %0;" : "+l"(d) : "l"(a), "l"(b));
}

// ---------------- main kernel: 128x64-tile register GEMM + argmax ----------
__global__ __launch_bounds__(TPB, 2)
void vq_kernel(const float* __restrict__ lat, const float* __restrict__ cb,
               float* __restrict__ out) {
    __shared__ unsigned long long sp [K2 * PTILE];   // points [k2][p]     32 KB
    __shared__ unsigned long long sck[K2 * CTILE];   // codes  [k2][c^kq]  16 KB

    const int tid = threadIdx.x;
    const int tx  = tid & 15;     // owns codes  {tx+16j}
    const int ty  = tid >> 4;     // owns points {ty*8 .. ty*8+7}
    const int pbase = blockIdx.x * PTILE;

    // ---- load 128 points -> smem [k2][p] (coalesced float4 gmem reads) ----
    const float4* latq = reinterpret_cast<const float4*>(lat) + (size_t)pbase * 16;
#pragma unroll
    for (int it = 0; it < (PTILE * 16) / TPB; it++) {   // 8 iters
        int idx = tid + it * TPB;
        int p = idx >> 4, kq = idx & 15;                // point p, dims 4kq..4kq+3
        float4 v = latq[idx];
        sp[(2 * kq)     * PTILE + p] = pack2(v.x, v.y);
        sp[(2 * kq + 1) * PTILE + p] = pack2(v.z, v.w);
    }

    float bestv[8];
    int   besti[8];
#pragma unroll
    for (int i = 0; i < 8; i++) { bestv[i] = -3.0e38f; besti[i] = 0; }

    const float4* cbq = reinterpret_cast<const float4*>(cb);

    for (int t = 0; t < NT; t++) {
        __syncthreads();   // previous tile fully consumed
        // ---- 64-code tile -> smem [k2][c ^ kq] (swizzle: conflict-free) ----
#pragma unroll
        for (int it = 0; it < (CTILE * 16) / TPB; it++) {   // 4 iters
            int idx = tid + it * TPB;
            int c = idx >> 4, kq = idx & 15;
            float4 v = cbq[(size_t)t * CTILE * 16 + idx];
            int cs = (c & 0x30) | ((c ^ kq) & 15);
            sck[(2 * kq)     * CTILE + cs] = pack2(v.x, v.y);
            sck[(2 * kq + 1) * CTILE + cs] = pack2(v.z, v.w);
        }
        __syncthreads();

        unsigned long long acc[8][4];
#pragma unroll
        for (int i = 0; i < 8; i++)
#pragma unroll
            for (int j = 0; j < 4; j++) acc[i][j] = 0ull;

#pragma unroll 4
        for (int kq = 0; kq < 16; kq++) {
            unsigned long long blo[4], bhi[4];   // 4 codes, dims 4kq..4kq+3
#pragma unroll
            for (int j = 0; j < 4; j++) {
                int cs = 16 * j + (tx ^ kq);
                blo[j] = sck[(2 * kq)     * CTILE + cs];
                bhi[j] = sck[(2 * kq + 1) * CTILE + cs];
            }
#pragma unroll
            for (int i2 = 0; i2 < 4; i2++) {
                // two adjacent points per 16B LDS (broadcast across tx lanes)
                ulonglong2 alo = *reinterpret_cast<const ulonglong2*>(
                    &sp[(2 * kq)     * PTILE + ty * 8 + 2 * i2]);
                ulonglong2 ahi = *reinterpret_cast<const ulonglong2*>(
                    &sp[(2 * kq + 1) * PTILE + ty * 8 + 2 * i2]);
#pragma unroll
                for (int j = 0; j < 4; j++) {
                    ffma2(acc[2 * i2][j],     alo.x, blo[j]);
                    ffma2(acc[2 * i2][j],     ahi.x, bhi[j]);
                    ffma2(acc[2 * i2 + 1][j], alo.y, blo[j]);
                    ffma2(acc[2 * i2 + 1][j], ahi.y, bhi[j]);
                }
            }
        }

        // ---- epilogue: score = dot - 0.5||c||^2, running argmax ----
#pragma unroll
        for (int j = 0; j < 4; j++) {
            const int cidx = t * CTILE + tx + 16 * j;
            const float ch = __ldg(&g_c2h[cidx]);
#pragma unroll
            for (int i = 0; i < 8; i++) {
                float ax, ay;
                upk(acc[i][j], ax, ay);
                float s = (ax - ch) + ay;
                if (s > bestv[i]) { bestv[i] = s; besti[i] = cidx; }
            }
        }
    }

    // ---- cross-thread reduction over the 16 code-columns per point ----
    __syncthreads();                       // compute done; reuse sck as scratch
    unsigned long long* red = sck;         // 128 x 16 u64 = 16 KB
#pragma unroll
    for (int i = 0; i < 8; i++) {
        int p = ty * 8 + i;
        red[p * 16 + (tx ^ (p & 15))] =
            ((unsigned long long)(unsigned)besti[i] << 32) |
            (unsigned long long)__float_as_uint(bestv[i]);
    }
    __syncthreads();

    if (tid < PTILE) {
        float bv = -3.0e38f; int bi = 0x7fffffff;
#pragma unroll
        for (int x = 0; x < 16; x++) {
            unsigned long long e = red[tid * 16 + (x ^ (tid & 15))];
            float s  = __uint_as_float((unsigned)(e & 0xffffffffu));
            int   ei = (int)(e >> 32);
            if (s > bv || (s == bv && ei < bi)) { bv = s; bi = ei; }
        }
        out[pbase + tid] = (float)bi;      // float32 output (verified contract)
    }
}

// ---------------- launch: proven input identification ----------------
extern "C" void kernel_launch(void* const* d_in, const int* in_sizes, int n_in,
                              void* d_out, int out_size) {
    const float* lat = (const float*)d_in[0];
    const float* cb  = (n_in > 1) ? (const float*)d_in[1] : (const float*)d_in[0];

    int cb_idx = -1, lat_idx = -1;
    for (int i = 0; i < n_in; i++) {
        if (in_sizes[i] == 524288)  cb_idx  = i;   // codebook (element semantics)
        if (in_sizes[i] == 8388608) lat_idx = i;   // latents  (byte semantics)
    }
    if (cb_idx >= 0) {
        cb = (const float*)d_in[cb_idx];
        for (int i = 0; i < n_in; i++)
            if (i != cb_idx && (in_sizes[i] == 2097152 || in_sizes[i] == 8388608)) {
                lat = (const float*)d_in[i]; break;
            }
    } else if (lat_idx >= 0) {
        lat = (const float*)d_in[lat_idx];
        for (int i = 0; i < n_in; i++)
            if (i != lat_idx && in_sizes[i] == 2097152) { cb = (const float*)d_in[i]; break; }
    }

    float* out = (float*)d_out;
    c2_kernel<<<NCODES / 256, 256>>>(cb);
    vq_kernel<<<NPTS / PTILE, TPB>>>(lat, cb, out);
}

// round 10
// speedup vs baseline: 5.5783x; 2.1141x over previous
#include <cuda_runtime.h>
#include <cuda_bf16.h>
#include <cstdint>

#define KDIM   64
#define NPTS   32768
#define NCODES 8192
#define PTILE  128
#define CTILE  64
#define NT     (NCODES / CTILE)    // 128 code tiles
#define TPB    256

// ---------------- device scratch (no allocations allowed) ----------------
__device__ __nv_bfloat16 g_lah[NPTS * KDIM];
__device__ __nv_bfloat16 g_lal[NPTS * KDIM];
__device__ __nv_bfloat16 g_cbh[NCODES * KDIM];
__device__ __nv_bfloat16 g_cbl[NCODES * KDIM];
__device__ float g_c2h[NCODES];            // 0.5*||c||^2 (fp32 exact)
__device__ int2  g_top2[NPTS];             // top-2 candidates per point

// ---------------- helpers ----------------
__device__ __forceinline__ uint32_t smem_u32(const void* p) {
    uint32_t a;
    asm("{ .reg .u64 t; cvta.to.shared.u64 t, %1; cvt.u32.u64 %0, t; }"
        : "=r"(a) : "l"(p));
    return a;
}
#define LDSM4(r, a)                                                          \
    asm volatile("ldmatrix.sync.aligned.m8n8.x4.shared.b16 {%0,%1,%2,%3}, [%4];" \
        : "=r"((r)[0]), "=r"((r)[1]), "=r"((r)[2]), "=r"((r)[3]) : "r"(a))

#define MMA(D, A, B0, B1)                                                    \
    asm volatile("mma.sync.aligned.m16n8k16.row.col.f32.bf16.bf16.f32 "      \
        "{%0,%1,%2,%3}, {%4,%5,%6,%7}, {%8,%9}, {%0,%1,%2,%3};"              \
        : "+f"((D)[0]), "+f"((D)[1]), "+f"((D)[2]), "+f"((D)[3])             \
        : "r"((A)[0]), "r"((A)[1]), "r"((A)[2]), "r"((A)[3]),                \
          "r"(B0), "r"(B1))

#define TOP2(V1, I1, V2, I2, s, idx) do {                                    \
    if ((s) > (V1)) { V2 = V1; I2 = I1; V1 = (s); I1 = (idx); }              \
    else if ((s) > (V2)) { V2 = (s); I2 = (idx); }                           \
} while (0)

__device__ __forceinline__ void merge2(float& v1, int& i1, float& v2, int& i2,
                                       float ov1, int oi1, float ov2, int oi2) {
    if (ov1 > v1) {
        if (v1 >= ov2) { v2 = v1; i2 = i1; } else { v2 = ov2; i2 = oi2; }
        v1 = ov1; i1 = oi1;
    } else if (ov1 > v2) { v2 = ov1; i2 = oi1; }
}

// ---------------- prekernels ----------------
__global__ void split_lat(const float* __restrict__ x) {
    int i = blockIdx.x * blockDim.x + threadIdx.x;
    float v = x[i];
    __nv_bfloat16 h = __float2bfloat16(v);
    g_lah[i] = h;
    g_lal[i] = __float2bfloat16(v - __bfloat162float(h));
}
__global__ void split_cb(const float* __restrict__ x) {
    int i = blockIdx.x * blockDim.x + threadIdx.x;
    float v = x[i];
    __nv_bfloat16 h = __float2bfloat16(v);
    g_cbh[i] = h;
    g_cbl[i] = __float2bfloat16(v - __bfloat162float(h));
}
__global__ void c2k(const float* __restrict__ cb) {
    int i = blockIdx.x * blockDim.x + threadIdx.x;
    const float* row = cb + (size_t)i * KDIM;
    float s = 0.f;
#pragma unroll
    for (int j = 0; j < KDIM; j++) s = fmaf(row[j], row[j], s);
    g_c2h[i] = 0.5f * s;
}

// ---------------- B-tile staging (swizzled, double-buffered) ----------------
__device__ __forceinline__ void stage_B(char* sB, float (*c2s)[CTILE],
                                        int tid, int t, int b) {
    const uint4* srch = reinterpret_cast<const uint4*>(g_cbh) + (size_t)t * 512;
    const uint4* srcl = reinterpret_cast<const uint4*>(g_cbl) + (size_t)t * 512;
#pragma unroll
    for (int i = 0; i < 2; i++) {                  // 512 chunks / 256 threads
        int id = tid + i * TPB;
        int r = id >> 3, c = id & 7;
        int off = b * 16384 + r * 128 + ((c ^ (r & 7)) * 16);
        *reinterpret_cast<uint4*>(sB + off)        = srch[id];
        *reinterpret_cast<uint4*>(sB + off + 8192) = srcl[id];
    }
    if (tid < CTILE) c2s[b][tid] = g_c2h[t * CTILE + tid];
}

// ---------------- main HMMA kernel ----------------
__global__ __launch_bounds__(TPB)
void vq_mma() {
    __shared__ __align__(16) uint4 sBq[2048];      // 32 KB: A staging, then B x2
    __shared__ float c2s[2][CTILE];
    char* sB = reinterpret_cast<char*>(sBq);
    const uint32_t sb = smem_u32(sBq);

    const int tid = threadIdx.x, lane = tid & 31, w = tid >> 5;
    const int pbase = blockIdx.x * PTILE;

    // ---- stage A (both splits) swizzled: [split][128 rows][128 B] ----
    {
        const uint4* srch = reinterpret_cast<const uint4*>(g_lah) + (size_t)pbase * 8;
        const uint4* srcl = reinterpret_cast<const uint4*>(g_lal) + (size_t)pbase * 8;
#pragma unroll
        for (int i = 0; i < 4; i++) {              // 1024 chunks / 256 threads
            int id = tid + i * TPB;
            int r = id >> 3, c = id & 7;
            int off = r * 128 + ((c ^ (r & 7)) * 16);
            *reinterpret_cast<uint4*>(sB + off)         = srch[id];
            *reinterpret_cast<uint4*>(sB + 16384 + off) = srcl[id];
        }
    }
    __syncthreads();

    // ---- A fragments into registers (held for all 128 tiles) ----
    uint32_t Ah[4][4], Al[4][4];
    {
        int r = w * 16 + (lane & 15);
        int ch = lane >> 4;                        // 0/1 : low/high 16B of kchunk
#pragma unroll
        for (int kc = 0; kc < 4; kc++) {
            int c = kc * 2 + ch;
            uint32_t addr = sb + r * 128 + ((c ^ (r & 7)) * 16);
            LDSM4(Ah[kc], addr);
            LDSM4(Al[kc], addr + 16384);
        }
    }
    __syncthreads();                               // A smem now reusable for B

    float v1a = -3.0e38f, v2a = -3.0e38f, v1b = -3.0e38f, v2b = -3.0e38f;
    int   i1a = 0, i2a = 1, i1b = 0, i2b = 1;

    stage_B(sB, c2s, tid, 0, 0);
    __syncthreads();

    for (int t = 0; t < NT; t++) {
        const int b = t & 1;
        if (t + 1 < NT) stage_B(sB, c2s, tid, t + 1, b ^ 1);
        const uint32_t bbase = sb + b * 16384;

#pragma unroll
        for (int n = 0; n < 8; n++) {
            uint32_t Bh[4][2], Bl[4][2];
            {
                int row = n * 8 + (lane & 7);
                int chq = (lane >> 3) & 3;
#pragma unroll
                for (int p = 0; p < 2; p++) {
                    int c = p * 4 + chq;
                    uint32_t addr = bbase + row * 128 + ((c ^ (row & 7)) * 16);
                    uint32_t tmp[4];
                    LDSM4(tmp, addr);
                    Bh[2*p][0] = tmp[0]; Bh[2*p][1] = tmp[1];
                    Bh[2*p+1][0] = tmp[2]; Bh[2*p+1][1] = tmp[3];
                    LDSM4(tmp, addr + 8192);
                    Bl[2*p][0] = tmp[0]; Bl[2*p][1] = tmp[1];
                    Bl[2*p+1][0] = tmp[2]; Bl[2*p+1][1] = tmp[3];
                }
            }
            float D[4] = {0.f, 0.f, 0.f, 0.f};
#pragma unroll
            for (int kc = 0; kc < 4; kc++) {
                MMA(D, Ah[kc], Bh[kc][0], Bh[kc][1]);   // hi*hi
                MMA(D, Ah[kc], Bl[kc][0], Bl[kc][1]);   // hi*lo
                MMA(D, Al[kc], Bh[kc][0], Bh[kc][1]);   // lo*hi
            }
            // ---- epilogue: score = dot - 0.5||c||^2, top-2 update ----
            int c0 = n * 8 + 2 * (lane & 3);
            int g0 = t * CTILE + c0;
            float ch0 = c2s[b][c0], ch1 = c2s[b][c0 + 1];
            float s0 = D[0] - ch0, s1 = D[1] - ch1;
            float s2 = D[2] - ch0, s3 = D[3] - ch1;
            TOP2(v1a, i1a, v2a, i2a, s0, g0);
            TOP2(v1a, i1a, v2a, i2a, s1, g0 + 1);
            TOP2(v1b, i1b, v2b, i2b, s2, g0);
            TOP2(v1b, i1b, v2b, i2b, s3, g0 + 1);
        }
        __syncthreads();
    }

    // ---- merge top-2 across the 4 lanes sharing each row ----
#pragma unroll
    for (int off = 1; off <= 2; off <<= 1) {
        float ov1 = __shfl_xor_sync(~0u, v1a, off);
        int   oi1 = __shfl_xor_sync(~0u, i1a, off);
        float ov2 = __shfl_xor_sync(~0u, v2a, off);
        int   oi2 = __shfl_xor_sync(~0u, i2a, off);
        merge2(v1a, i1a, v2a, i2a, ov1, oi1, ov2, oi2);
        ov1 = __shfl_xor_sync(~0u, v1b, off);
        oi1 = __shfl_xor_sync(~0u, i1b, off);
        ov2 = __shfl_xor_sync(~0u, v2b, off);
        oi2 = __shfl_xor_sync(~0u, i2b, off);
        merge2(v1b, i1b, v2b, i2b, ov1, oi1, ov2, oi2);
    }
    if ((lane & 3) == 0) {
        int r0 = lane >> 2;
        g_top2[pbase + w * 16 + r0]     = make_int2(i1a, i2a);
        g_top2[pbase + w * 16 + r0 + 8] = make_int2(i1b, i2b);
    }
}

// ---------------- exact fp32 rescore of the two candidates ----------------
__global__ void rescore_kernel(const float* __restrict__ lat,
                               const float* __restrict__ cb,
                               float* __restrict__ out) {
    int p = blockIdx.x * blockDim.x + threadIdx.x;
    int2 cand = g_top2[p];
    const float4* x = reinterpret_cast<const float4*>(lat + (size_t)p * KDIM);
    float4 xr[KDIM / 4];
#pragma unroll
    for (int q = 0; q < KDIM / 4; q++) xr[q] = x[q];

    float sc[2];
    int   id[2] = {cand.x, cand.y};
#pragma unroll
    for (int j = 0; j < 2; j++) {
        const float4* c = reinterpret_cast<const float4*>(cb + (size_t)id[j] * KDIM);
        float a0 = 0.f, a1 = 0.f, a2 = 0.f, a3 = 0.f;
#pragma unroll
        for (int q = 0; q < KDIM / 4; q++) {
            float4 cv = c[q];
            a0 = fmaf(xr[q].x, cv.x, a0);
            a1 = fmaf(xr[q].y, cv.y, a1);
            a2 = fmaf(xr[q].z, cv.z, a2);
            a3 = fmaf(xr[q].w, cv.w, a3);
        }
        sc[j] = ((a0 + a1) + (a2 + a3)) - g_c2h[id[j]];
    }
    int best = (sc[1] > sc[0] || (sc[1] == sc[0] && id[1] < id[0])) ? id[1] : id[0];
    out[p] = (float)best;
}

// ---------------- launch ----------------
extern "C" void kernel_launch(void* const* d_in, const int* in_sizes, int n_in,
                              void* d_out, int out_size) {
    const float* lat = (const float*)d_in[0];
    const float* cb  = (n_in > 1) ? (const float*)d_in[1] : (const float*)d_in[0];
    int cb_idx = -1, lat_idx = -1;
    for (int i = 0; i < n_in; i++) {
        if (in_sizes[i] == 524288)  cb_idx  = i;
        if (in_sizes[i] == 8388608) lat_idx = i;
    }
    if (cb_idx >= 0) {
        cb = (const float*)d_in[cb_idx];
        for (int i = 0; i < n_in; i++)
            if (i != cb_idx && (in_sizes[i] == 2097152 || in_sizes[i] == 8388608)) {
                lat = (const float*)d_in[i]; break;
            }
    } else if (lat_idx >= 0) {
        lat = (const float*)d_in[lat_idx];
        for (int i = 0; i < n_in; i++)
            if (i != lat_idx && in_sizes[i] == 2097152) { cb = (const float*)d_in[i]; break; }
    }
    float* out = (float*)d_out;

    split_lat<<<(NPTS * KDIM) / 256, 256>>>(lat);
    split_cb<<<(NCODES * KDIM) / 256, 256>>>(cb);
    c2k<<<NCODES / 256, 256>>>(cb);
    vq_mma<<<NPTS / PTILE, TPB>>>();
    rescore_kernel<<<NPTS / 128, 128>>>(lat, cb, out);
}